// round 1
// baseline (speedup 1.0000x reference)
#include <cuda_runtime.h>
#include <cstdint>
#include <cstdio>

#define B_    8
#define N1_   16384
#define N2_   2048
#define C1_   128
#define C2_   256
#define INCH_ 384
#define H1_   256
#define H2_   128
#define M_    (B_ * N1_)      // 131072 rows
#define STAT_ROWS 256
#define STAT_BLKS (M_ / STAT_ROWS)  // 512
#define BN_EPS 1e-5f

// ---------------- scratch (device globals; no cudaMalloc allowed) ----------------
__device__ float g_x  [(size_t)M_ * INCH_];   // concat(points1, interp)  [M,384]
__device__ float g_h1 [(size_t)M_ * H1_];     // GEMM1 out (pre-BN)       [M,256]
__device__ float g_h2 [(size_t)M_ * H2_];     // GEMM2 out (pre-BN)       [M,128]
__device__ float g_Wt1[INCH_ * H1_];          // W1^T  [K=384][N=256]
__device__ float g_Wt2[H1_ * H2_];            // W2^T  [K=256][N=128]
__device__ float g_psum[STAT_BLKS * H1_];
__device__ float g_psq [STAT_BLKS * H1_];
__device__ float g_scale1[H1_], g_shift1[H1_];
__device__ float g_scale2[H2_], g_shift2[H2_];

// ---------------- weight transpose: Wt[k][o] = W[o][k] ----------------
__global__ void transpose_kernel(const float* __restrict__ W, float* __restrict__ Wt,
                                 int O, int I) {
    int idx = blockIdx.x * 256 + threadIdx.x;
    if (idx < O * I) {
        int o = idx / I, i = idx % I;
        Wt[i * O + o] = W[idx];
    }
}

// ---------------- 3-NN + inverse-distance interpolation + concat ----------------
// grid: (N1/128, B), block: 128 threads. One query per thread for the search,
// then warp-cooperative gather for the feature interpolation.
__global__ __launch_bounds__(128)
void knn_interp_kernel(const float* __restrict__ xyz1, const float* __restrict__ xyz2,
                       const float* __restrict__ points1, const float* __restrict__ points2,
                       float* __restrict__ x_out) {
    __shared__ float sx[N2_], sy[N2_], sz[N2_];
    __shared__ int   s_idx[128][3];
    __shared__ float s_w  [128][3];

    const int b   = blockIdx.y;
    const int q0  = blockIdx.x * 128;
    const int tid = threadIdx.x;

    const float* x2 = xyz2 + (size_t)b * N2_ * 3;
    for (int j = tid; j < N2_; j += 128) {
        sx[j] = x2[j * 3 + 0];
        sy[j] = x2[j * 3 + 1];
        sz[j] = x2[j * 3 + 2];
    }
    __syncthreads();

    // ---- phase 1: brute-force top-3 smallest distances ----
    const int q = q0 + tid;
    const float* p = xyz1 + ((size_t)b * N1_ + q) * 3;
    const float px = p[0], py = p[1], pz = p[2];

    float d0 = 1e30f, d1 = 1e30f, d2 = 1e30f;
    int   i0 = 0, i1 = 0, i2 = 0;
#pragma unroll 8
    for (int j = 0; j < N2_; j++) {
        float dx = px - sx[j];
        float dy = py - sy[j];
        float dz = pz - sz[j];
        float d  = fmaf(dx, dx, fmaf(dy, dy, dz * dz));
        if (d < d0)      { d2 = d1; i2 = i1; d1 = d0; i1 = i0; d0 = d; i0 = j; }
        else if (d < d1) { d2 = d1; i2 = i1; d1 = d;  i1 = j; }
        else if (d < d2) { d2 = d;  i2 = j; }
    }
    d0 = fmaxf(d0, 1e-10f); d1 = fmaxf(d1, 1e-10f); d2 = fmaxf(d2, 1e-10f);
    float w0 = 1.0f / d0, w1 = 1.0f / d1, w2 = 1.0f / d2;
    float inv = 1.0f / fmaxf(w0 + w1 + w2, 1e-8f);
    s_idx[tid][0] = i0; s_idx[tid][1] = i1; s_idx[tid][2] = i2;
    s_w[tid][0] = w0 * inv; s_w[tid][1] = w1 * inv; s_w[tid][2] = w2 * inv;
    __syncthreads();

    // ---- phase 2: warp-cooperative gather + concat write ----
    const int warp = tid >> 5, lane = tid & 31;
    const float* p2  = points2 + (size_t)b * N2_ * C2_;
    const float* p1b = points1 + ((size_t)b * N1_ + q0) * C1_;
    float* xb = x_out + ((size_t)b * N1_ + q0) * INCH_;

    for (int lq = warp; lq < 128; lq += 4) {
        const int   j0 = s_idx[lq][0], j1 = s_idx[lq][1], j2 = s_idx[lq][2];
        const float a0 = s_w[lq][0],   a1 = s_w[lq][1],   a2 = s_w[lq][2];
        const float* r0 = p2 + (size_t)j0 * C2_;
        const float* r1 = p2 + (size_t)j1 * C2_;
        const float* r2 = p2 + (size_t)j2 * C2_;
        float* xrow = xb + (size_t)lq * INCH_;
#pragma unroll
        for (int c = lane; c < C2_; c += 32)
            xrow[C1_ + c] = fmaf(a0, r0[c], fmaf(a1, r1[c], a2 * r2[c]));
        const float* pr = p1b + (size_t)lq * C1_;
#pragma unroll
        for (int c = lane; c < C1_; c += 32)
            xrow[c] = pr[c];
    }
}

// ---------------- SGEMM: C[M,N] = op(A)[M,K] @ Bt[K,N] ----------------
// 128x128 tile, TK=8, 256 threads, 8x8 microtile. Optional fused BN+ReLU on A
// (per-K-channel scale/shift, then max(.,0)).
template <int K, int N, bool BN>
__global__ __launch_bounds__(256)
void gemm_kernel(const float* __restrict__ A, const float* __restrict__ Bt,
                 const float* __restrict__ scale, const float* __restrict__ shift,
                 float* __restrict__ C) {
    __shared__ float As[8][128];
    __shared__ float Bs[8][128];

    const int tid = threadIdx.x;
    const int m0 = blockIdx.x * 128;
    const int n0 = blockIdx.y * 128;

    const int ar = tid >> 1;          // A tile row 0..127
    const int ac = (tid & 1) * 4;     // A tile col 0 or 4
    const int br = tid >> 5;          // B tile row 0..7
    const int bc = (tid & 31) * 4;    // B tile col
    const int ty = tid >> 4, tx = tid & 15;

    float acc[8][8];
#pragma unroll
    for (int i = 0; i < 8; i++)
#pragma unroll
        for (int j = 0; j < 8; j++) acc[i][j] = 0.0f;

    for (int k0 = 0; k0 < K; k0 += 8) {
        float4 av = *(const float4*)(A + (size_t)(m0 + ar) * K + k0 + ac);
        if (BN) {
            av.x = fmaxf(fmaf(av.x, scale[k0 + ac + 0], shift[k0 + ac + 0]), 0.0f);
            av.y = fmaxf(fmaf(av.y, scale[k0 + ac + 1], shift[k0 + ac + 1]), 0.0f);
            av.z = fmaxf(fmaf(av.z, scale[k0 + ac + 2], shift[k0 + ac + 2]), 0.0f);
            av.w = fmaxf(fmaf(av.w, scale[k0 + ac + 3], shift[k0 + ac + 3]), 0.0f);
        }
        As[ac + 0][ar] = av.x;
        As[ac + 1][ar] = av.y;
        As[ac + 2][ar] = av.z;
        As[ac + 3][ar] = av.w;
        *(float4*)&Bs[br][bc] = *(const float4*)(Bt + (size_t)(k0 + br) * N + n0 + bc);
        __syncthreads();

#pragma unroll
        for (int k = 0; k < 8; k++) {
            float a[8], bb[8];
            *(float4*)(a)      = *(const float4*)&As[k][ty * 8];
            *(float4*)(a + 4)  = *(const float4*)&As[k][ty * 8 + 4];
            *(float4*)(bb)     = *(const float4*)&Bs[k][tx * 8];
            *(float4*)(bb + 4) = *(const float4*)&Bs[k][tx * 8 + 4];
#pragma unroll
            for (int i = 0; i < 8; i++)
#pragma unroll
                for (int j = 0; j < 8; j++)
                    acc[i][j] = fmaf(a[i], bb[j], acc[i][j]);
        }
        __syncthreads();
    }

#pragma unroll
    for (int i = 0; i < 8; i++) {
        float* cp = C + (size_t)(m0 + ty * 8 + i) * N + n0 + tx * 8;
        *(float4*)(cp)     = make_float4(acc[i][0], acc[i][1], acc[i][2], acc[i][3]);
        *(float4*)(cp + 4) = make_float4(acc[i][4], acc[i][5], acc[i][6], acc[i][7]);
    }
}

// ---------------- BN stats: per-block partial sums (deterministic) ----------------
template <int C>
__global__ void stats_kernel(const float* __restrict__ H,
                             float* __restrict__ psum, float* __restrict__ psq) {
    const int c = threadIdx.x;  // C threads
    size_t base = (size_t)blockIdx.x * STAT_ROWS * C + c;
    float s = 0.0f, s2 = 0.0f;
#pragma unroll 4
    for (int r = 0; r < STAT_ROWS; r++) {
        float v = H[base + (size_t)r * C];
        s += v;
        s2 = fmaf(v, v, s2);
    }
    psum[blockIdx.x * C + c] = s;
    psq [blockIdx.x * C + c] = s2;
}

template <int C>
__global__ void reduce_kernel(const float* __restrict__ psum, const float* __restrict__ psq,
                              const float* __restrict__ gamma, const float* __restrict__ beta,
                              float* __restrict__ scale, float* __restrict__ shift) {
    const int c = threadIdx.x;
    float s = 0.0f, s2 = 0.0f;
    for (int i = 0; i < STAT_BLKS; i++) {
        s  += psum[i * C + c];
        s2 += psq [i * C + c];
    }
    const float invn = 1.0f / (float)M_;
    float mean = s * invn;
    float var  = s2 * invn - mean * mean;
    float sc = gamma[c] * rsqrtf(var + BN_EPS);
    scale[c] = sc;
    shift[c] = beta[c] - mean * sc;
}

// ---------------- final BN2 + ReLU ----------------
__global__ void apply_kernel(const float* __restrict__ H,
                             const float* __restrict__ scale, const float* __restrict__ shift,
                             float* __restrict__ out) {
    size_t i = (size_t)blockIdx.x * blockDim.x + threadIdx.x;   // float4 index
    float4 v = ((const float4*)H)[i];
    int c = (int)((i * 4) & (H2_ - 1));
    float4 o;
    o.x = fmaxf(fmaf(v.x, scale[c + 0], shift[c + 0]), 0.0f);
    o.y = fmaxf(fmaf(v.y, scale[c + 1], shift[c + 1]), 0.0f);
    o.z = fmaxf(fmaf(v.z, scale[c + 2], shift[c + 2]), 0.0f);
    o.w = fmaxf(fmaf(v.w, scale[c + 3], shift[c + 3]), 0.0f);
    ((float4*)out)[i] = o;
}

// ---------------- host launcher ----------------
extern "C" void kernel_launch(void* const* d_in, const int* in_sizes, int n_in,
                              void* d_out, int out_size) {
    const float* xyz1    = (const float*)d_in[0];
    const float* xyz2    = (const float*)d_in[1];
    const float* points1 = (const float*)d_in[2];
    const float* points2 = (const float*)d_in[3];
    const float* W1      = (const float*)d_in[4];
    // d_in[5] = b1 : cancels under BatchNorm (mean subtraction) -> unused
    const float* gamma1  = (const float*)d_in[6];
    const float* beta1   = (const float*)d_in[7];
    const float* W2      = (const float*)d_in[8];
    // d_in[9] = b2 : cancels under BatchNorm -> unused
    const float* gamma2  = (const float*)d_in[10];
    const float* beta2   = (const float*)d_in[11];
    float* out = (float*)d_out;

    float *px, *ph1, *ph2, *pwt1, *pwt2, *pps, *ppq, *psc1, *psh1, *psc2, *psh2;
    cudaGetSymbolAddress((void**)&px,   g_x);
    cudaGetSymbolAddress((void**)&ph1,  g_h1);
    cudaGetSymbolAddress((void**)&ph2,  g_h2);
    cudaGetSymbolAddress((void**)&pwt1, g_Wt1);
    cudaGetSymbolAddress((void**)&pwt2, g_Wt2);
    cudaGetSymbolAddress((void**)&pps,  g_psum);
    cudaGetSymbolAddress((void**)&ppq,  g_psq);
    cudaGetSymbolAddress((void**)&psc1, g_scale1);
    cudaGetSymbolAddress((void**)&psh1, g_shift1);
    cudaGetSymbolAddress((void**)&psc2, g_scale2);
    cudaGetSymbolAddress((void**)&psh2, g_shift2);

    // weight transposes (tiny)
    transpose_kernel<<<(H1_ * INCH_ + 255) / 256, 256>>>(W1, pwt1, H1_, INCH_);
    transpose_kernel<<<(H2_ * H1_  + 255) / 256, 256>>>(W2, pwt2, H2_, H1_);

    // 3-NN + interpolate + concat -> g_x [M,384]
    {
        dim3 grid(N1_ / 128, B_);
        knn_interp_kernel<<<grid, 128>>>(xyz1, xyz2, points1, points2, px);
    }

    // GEMM1: g_h1 = g_x @ W1^T   (bias dropped: cancels in BN)
    {
        dim3 grid(M_ / 128, H1_ / 128);
        gemm_kernel<INCH_, H1_, false><<<grid, 256>>>(px, pwt1, nullptr, nullptr, ph1);
    }

    // BN1 stats -> scale1/shift1
    stats_kernel<H1_><<<STAT_BLKS, H1_>>>(ph1, pps, ppq);
    reduce_kernel<H1_><<<1, H1_>>>(pps, ppq, gamma1, beta1, psc1, psh1);

    // GEMM2 with fused BN1+ReLU on the A operand: g_h2 = relu(bn1(g_h1)) @ W2^T
    {
        dim3 grid(M_ / 128, H2_ / 128);
        gemm_kernel<H1_, H2_, true><<<grid, 256>>>(ph1, pwt2, psc1, psh1, ph2);
    }

    // BN2 stats -> scale2/shift2
    stats_kernel<H2_><<<STAT_BLKS, H2_>>>(ph2, pps, ppq);
    reduce_kernel<H2_><<<1, H2_>>>(pps, ppq, gamma2, beta2, psc2, psh2);

    // final BN2 + ReLU -> d_out [M,128]
    {
        size_t n4 = (size_t)M_ * H2_ / 4;
        apply_kernel<<<(unsigned)(n4 / 256), 256>>>(ph2, psc2, psh2, out);
    }
}